// round 17
// baseline (speedup 1.0000x reference)
#include <cuda_runtime.h>
#include <cuda_fp16.h>
#include <cstdint>

#define BHN   48
#define SEQ   1024
#define HD    64
#define TQ    128
#define TK    64
#define NQT   8           // SEQ / TQ
#define NTH   256
#define LAM   0.01f
#define EPSV  1e-6f
#define CLV   20.0f
#define SCALE 0.125f

// half rows padded to 72 halves = 144 bytes
#define RSTR  144
#define QH_OFF 0
#define KH_OFF (QH_OFF + 128 * RSTR)   // 18432
#define VH_OFF (KH_OFF +  64 * RSTR)   // 27648
#define WH_OFF (VH_OFF +  64 * RSTR)   // 36864
#define WS_OFF (WH_OFF + 128 * RSTR)   // 55296
// raw fp32 cp.async staging (chunk h+1)
#define SGK_OFF (WS_OFF + 512)         // 55808, K raw [64][64] f32
#define SGV_OFF (SGK_OFF + 16384)      // 72192, V raw
#define SGC_OFF (SGV_OFF + 16384)      // 88576, cos [64][32] f32
#define SGS_OFF (SGC_OFF + 8192)       // 96768, sin
#define SM_TOTAL (SGS_OFF + 8192)      // 104960

__device__ __forceinline__ uint32_t s2u(const void* p) {
    uint32_t a;
    asm("{ .reg .u64 t; cvta.to.shared.u64 t, %1; cvt.u32.u64 %0, t; }" : "=r"(a) : "l"(p));
    return a;
}
__device__ __forceinline__ float sigm(float x) {
    float t;
    asm("tanh.approx.f32 %0, %1;" : "=f"(t) : "f"(x * 0.5f));
    return fmaf(t, 0.5f, 0.5f);
}
__device__ __forceinline__ void cpa16(uint32_t dst, const void* src) {
    asm volatile("cp.async.cg.shared.global [%0], [%1], 16;" :: "r"(dst), "l"(src));
}
__device__ __forceinline__ void ldsm4(uint32_t* r, uint32_t addr) {
    asm volatile("ldmatrix.sync.aligned.m8n8.x4.shared.b16 {%0,%1,%2,%3}, [%4];"
        : "=r"(r[0]), "=r"(r[1]), "=r"(r[2]), "=r"(r[3]) : "r"(addr));
}
__device__ __forceinline__ void ldsm4t(uint32_t* r, uint32_t addr) {
    asm volatile("ldmatrix.sync.aligned.m8n8.x4.trans.shared.b16 {%0,%1,%2,%3}, [%4];"
        : "=r"(r[0]), "=r"(r[1]), "=r"(r[2]), "=r"(r[3]) : "r"(addr));
}
__device__ __forceinline__ void mma16816(float* d, const uint32_t* a, const uint32_t* b) {
    asm volatile(
        "mma.sync.aligned.m16n8k16.row.col.f32.f16.f16.f32 "
        "{%0,%1,%2,%3}, {%4,%5,%6,%7}, {%8,%9}, {%0,%1,%2,%3};"
        : "+f"(d[0]), "+f"(d[1]), "+f"(d[2]), "+f"(d[3])
        : "r"(a[0]), "r"(a[1]), "r"(a[2]), "r"(a[3]), "r"(b[0]), "r"(b[1]));
}

__global__ void __launch_bounds__(NTH, 2)
rse_mma(const float* __restrict__ gq, const float* __restrict__ gk,
        const float* __restrict__ gv, const float* __restrict__ gcos,
        const float* __restrict__ gsin, float* __restrict__ gout)
{
    extern __shared__ char smem[];
    const uint32_t sb = s2u(smem);
    const int tid  = threadIdx.x;
    const int wid  = tid >> 5;     // warp owns query rows 16*wid..16*wid+15
    const int lane = tid & 31;
    const int idx  = blockIdx.x;
    const int qt   = (NQT - 1) - (idx / BHN);   // heavy q-tiles first
    const int bh   = idx % BHN;
    const int q0   = qt * TQ;
    const size_t base = (size_t)bh * SEQ * HD;

    const int lrow = tid >> 2;     // staging/convert row 0..63
    const int lqt  = tid & 3;      // quarter-row (16 floats)
    const uint32_t sgk = sb + SGK_OFF + lrow * 256 + lqt * 64;
    const uint32_t sgv = sb + SGV_OFF + lrow * 256 + lqt * 64;
    const uint32_t sgc = sb + SGC_OFF + lrow * 128 + lqt * 32;
    const uint32_t sgs = sb + SGS_OFF + lrow * 128 + lqt * 32;

    const int nchunk = 2 * qt + 2;

    // ---- prefetch chunk 0 raw K/V/cos/sin via cp.async ----
    {
        const float* ksrc = gk + base + (size_t)lrow * HD + lqt * 16;
        const float* vsrc = gv + base + (size_t)lrow * HD + lqt * 16;
        const float* csrc = gcos + lrow * 32 + lqt * 8;
        const float* ssrc = gsin + lrow * 32 + lqt * 8;
        #pragma unroll
        for (int j = 0; j < 4; j++) {
            cpa16(sgk + 16 * j, ksrc + 4 * j);
            cpa16(sgv + 16 * j, vsrc + 4 * j);
        }
        cpa16(sgc, csrc); cpa16(sgc + 16, csrc + 4);
        cpa16(sgs, ssrc); cpa16(sgs + 16, ssrc + 4);
        asm volatile("cp.async.commit_group;" ::: "memory");
    }

    // ---- load Q (half-row per thread), RoPE, fp16 -> QH ----
    {
        const int row  = tid >> 1;
        const int half = tid & 1;
        const float* src = gq + base + (size_t)(q0 + row) * HD + half * 32;
        const float* cc  = gcos + (q0 + row) * 32 + half * 16;
        const float* ss  = gsin + (q0 + row) * 32 + half * 16;
        __half2* dst = (__half2*)(smem + QH_OFF + row * RSTR + half * 64);
        #pragma unroll
        for (int j = 0; j < 8; j++) {
            float4 x = *(const float4*)(src + 4 * j);
            float2 c = *(const float2*)(cc + 2 * j);
            float2 s = *(const float2*)(ss + 2 * j);
            dst[2*j]   = __floats2half2_rn(x.x*c.x - x.y*s.x, x.y*c.x + x.x*s.x);
            dst[2*j+1] = __floats2half2_rn(x.z*c.y - x.w*s.y, x.w*c.y + x.z*s.y);
        }
    }
    __syncthreads();

    // ---- Q fragments (persistent): 32 bytes per k16 step ----
    uint32_t qf[4][4];
    {
        const int row = 16 * wid + (lane & 15);
        const uint32_t qb = sb + QH_OFF + row * RSTR + ((lane & 16) ? 16 : 0);
        #pragma unroll
        for (int ks = 0; ks < 4; ks++) ldsm4(qf[ks], qb + 32 * ks);
    }

    // ---- hoisted chunk-invariant addresses (k16 step = 32 bytes) ----
    uint32_t kfb[4];
    #pragma unroll
    for (int a2 = 0; a2 < 4; a2++) {
        int row = 16 * a2 + (lane & 7) + ((lane & 16) ? 8 : 0);
        kfb[a2] = sb + KH_OFF + row * RSTR + ((lane & 8) ? 16 : 0);
    }
    const uint32_t wab = sb + WH_OFF + (16 * wid + (lane & 15)) * RSTR
                       + ((lane & 16) ? 16 : 0);
    uint32_t vbb[4];
    #pragma unroll
    for (int c2 = 0; c2 < 4; c2++) {
        int row = (lane & 7) + ((lane & 8) ? 8 : 0);
        vbb[c2] = sb + VH_OFF + row * RSTR + 32 * c2 + ((lane & 16) ? 16 : 0);
    }
    const int ql = 16 * wid + (lane >> 2);
    const uint32_t wst0 = sb + WH_OFF + ql * RSTR + 4 * (lane & 3);
    const uint32_t wst1 = wst0 + 8 * RSTR;
    __half2* kdst = (__half2*)(smem + KH_OFF + lrow * RSTR + lqt * 32);
    __half2* vdst = (__half2*)(smem + VH_OFF + lrow * RSTR + lqt * 32);

    float od[8][4];
    #pragma unroll
    for (int c = 0; c < 8; c++)
        #pragma unroll
        for (int r = 0; r < 4; r++) od[c][r] = 0.f;
    float rem = 1.f, ws = 0.f;
    const int sq = 16 * wid + lane;      // scan query (lanes < 16)

    for (int h = 0; h < nchunk; h++) {
        const int k0 = h * TK;
        asm volatile("cp.async.wait_group 0;" ::: "memory");
        __syncthreads();   // P3(h-1) done with KH/VH/WH

        // ---- convert staged raw -> fp16 KH (RoPE) / VH ----
        {
            float4 kx[4], vx[4];
            float2 cx[4], sx[4];
            #pragma unroll
            for (int j = 0; j < 4; j++) {
                kx[j] = *(const float4*)(smem + (sgk - sb) + 16 * j);
                vx[j] = *(const float4*)(smem + (sgv - sb) + 16 * j);
            }
            #pragma unroll
            for (int j = 0; j < 4; j++) {
                cx[j] = *(const float2*)(smem + (sgc - sb) + 8 * j);
                sx[j] = *(const float2*)(smem + (sgs - sb) + 8 * j);
            }
            #pragma unroll
            for (int j = 0; j < 4; j++) {
                kdst[2*j]   = __floats2half2_rn(kx[j].x*cx[j].x - kx[j].y*sx[j].x,
                                                kx[j].y*cx[j].x + kx[j].x*sx[j].x);
                kdst[2*j+1] = __floats2half2_rn(kx[j].z*cx[j].y - kx[j].w*sx[j].y,
                                                kx[j].w*cx[j].y + kx[j].z*sx[j].y);
                vdst[2*j]   = __floats2half2_rn(vx[j].x, vx[j].y);
                vdst[2*j+1] = __floats2half2_rn(vx[j].z, vx[j].w);
            }
        }
        __syncthreads();   // fp16 tiles ready; own staging consumed

        // ---- prefetch chunk h+1 ----
        if (h + 1 < nchunk) {
            const int kn = k0 + TK;
            const float* ksrc = gk + base + (size_t)(kn + lrow) * HD + lqt * 16;
            const float* vsrc = gv + base + (size_t)(kn + lrow) * HD + lqt * 16;
            const float* csrc = gcos + (kn + lrow) * 32 + lqt * 8;
            const float* ssrc = gsin + (kn + lrow) * 32 + lqt * 8;
            #pragma unroll
            for (int j = 0; j < 4; j++) {
                cpa16(sgk + 16 * j, ksrc + 4 * j);
                cpa16(sgv + 16 * j, vsrc + 4 * j);
            }
            cpa16(sgc, csrc); cpa16(sgc + 16, csrc + 4);
            cpa16(sgs, ssrc); cpa16(sgs + 16, ssrc + 4);
            asm volatile("cp.async.commit_group;" ::: "memory");
        }

        // ---- P1: S[16q x 64k] = Q · K^T (HMMA), fused beta -> WH ----
        {
            float sd[8][4];
            #pragma unroll
            for (int nf = 0; nf < 8; nf++)
                #pragma unroll
                for (int r = 0; r < 4; r++) sd[nf][r] = 0.f;

            #pragma unroll
            for (int ks = 0; ks < 4; ks++) {
                uint32_t bf[8][2];
                #pragma unroll
                for (int a2 = 0; a2 < 4; a2++) {
                    uint32_t r[4];
                    ldsm4(r, kfb[a2] + 32 * ks);
                    bf[2*a2][0]   = r[0]; bf[2*a2][1]   = r[1];
                    bf[2*a2+1][0] = r[2]; bf[2*a2+1][1] = r[3];
                }
                #pragma unroll
                for (int nf = 0; nf < 8; nf++)
                    mma16816(sd[nf], qf[ks], bf[nf]);
            }
            const float pda = (float)(k0 - (q0 + ql)) * LAM;
            const float pdb = pda - 8.f * LAM;
            #pragma unroll
            for (int nf = 0; nf < 8; nf++) {
                const float klf = (float)(8 * nf + 2 * (lane & 3)) * LAM;
                float p0 = pda + klf;
                float b0 = sigm(fminf(fmaxf(fmaf(sd[nf][0], SCALE, p0      ), -CLV), CLV));
                float b1 = sigm(fminf(fmaxf(fmaf(sd[nf][1], SCALE, p0 + LAM), -CLV), CLV));
                __half2 h01 = __floats2half2_rn(b0, b1);
                asm volatile("st.shared.b32 [%0], %1;" :: "r"(wst0 + 16 * nf),
                             "r"(*(uint32_t*)&h01) : "memory");
                float p1 = pdb + klf;
                float b2 = sigm(fminf(fmaxf(fmaf(sd[nf][2], SCALE, p1      ), -CLV), CLV));
                float b3 = sigm(fminf(fmaxf(fmaf(sd[nf][3], SCALE, p1 + LAM), -CLV), CLV));
                __half2 h23 = __floats2half2_rn(b2, b3);
                asm volatile("st.shared.b32 [%0], %1;" :: "r"(wst1 + 16 * nf),
                             "r"(*(uint32_t*)&h23) : "memory");
            }
        }
        __syncwarp();

        // ---- scan: lanes < 16, thread = query sq ----
        if (lane < 16) {
            const int nvalid = min(64, max(0, sq + q0 - k0 + 1));
            uint4* wr = (uint4*)(smem + WH_OFF + sq * RSTR);
            #pragma unroll
            for (int g = 0; g < 8; g++) {
                uint4 u = wr[g];
                uint32_t* uw = (uint32_t*)&u;
                #pragma unroll
                for (int m = 0; m < 4; m++) {
                    float2 f = __half22float2(*(__half2*)&uw[m]);
                    int i = g * 8 + m * 2;
                    float w0 = (i < nvalid) ? f.x * rem : 0.f;
                    rem = fmaf(-w0, rem, rem);
                    float w1 = (i + 1 < nvalid) ? f.y * rem : 0.f;
                    rem = fmaf(-w1, rem, rem);
                    ws += w0 + w1;
                    __half2 o = __floats2half2_rn(w0, w1);
                    uw[m] = *(uint32_t*)&o;
                }
                rem = fmaxf(rem, EPSV);
                wr[g] = u;
            }
        }
        __syncwarp();

        // ---- P3: O[16q x 64d] += W · V (HMMA over keys) ----
        #pragma unroll
        for (int ks2 = 0; ks2 < 4; ks2++) {
            uint32_t af[4];
            ldsm4(af, wab + 32 * ks2);
            uint32_t vb[8][2];
            #pragma unroll
            for (int c2 = 0; c2 < 4; c2++) {
                uint32_t r[4];
                ldsm4t(r, vbb[c2] + ks2 * 16 * RSTR);
                vb[2*c2][0]   = r[0]; vb[2*c2][1]   = r[1];
                vb[2*c2+1][0] = r[2]; vb[2*c2+1][1] = r[3];
            }
            #pragma unroll
            for (int c = 0; c < 8; c++)
                mma16816(od[c], af, vb[c]);
        }
    }

    // ---- epilogue: share wsum, normalize O fragments, write out ----
    {
        float* wsF = (float*)(smem + WS_OFF);
        if (lane < 16) wsF[sq] = ws;
        __syncthreads();
        float inv0 = __fdividef(1.f, fmaxf(wsF[ql],     EPSV));
        float inv1 = __fdividef(1.f, fmaxf(wsF[ql + 8], EPSV));
        float* r0 = gout + base + (size_t)(q0 + ql) * HD;
        float* r1 = r0 + 8 * HD;
        #pragma unroll
        for (int c = 0; c < 8; c++) {
            const int dc = 8 * c + 2 * (lane & 3);
            float2 o0; o0.x = od[c][0] * inv0; o0.y = od[c][1] * inv0;
            *(float2*)(r0 + dc) = o0;
            float2 o1; o1.x = od[c][2] * inv1; o1.y = od[c][3] * inv1;
            *(float2*)(r1 + dc) = o1;
        }
    }
}

extern "C" void kernel_launch(void* const* d_in, const int* in_sizes, int n_in,
                              void* d_out, int out_size)
{
    (void)in_sizes; (void)n_in; (void)out_size;
    const float* q    = (const float*)d_in[0];
    const float* k    = (const float*)d_in[1];
    const float* v    = (const float*)d_in[2];
    const float* cosc = (const float*)d_in[3];
    const float* sinc = (const float*)d_in[4];
    float* out = (float*)d_out;

    cudaFuncSetAttribute(rse_mma, cudaFuncAttributeMaxDynamicSharedMemorySize,
                         SM_TOTAL);
    rse_mma<<<NQT * BHN, NTH, SM_TOTAL>>>(q, k, v, cosc, sinc, out);
}